// round 1
// baseline (speedup 1.0000x reference)
#include <cuda_runtime.h>

#define N_NODES 2048
#define N_EDGES 8192
#define EDGE_DIM 10
#define EH 32
#define HID 160
#define NW (HID*HID)                 // 25600
#define COL_B2 (EH*HID)              // 5120 : start of b2-term columns
#define COL_ROOT (EH*HID + HID)      // 5280 : start of root-term columns
#define NCOLS (EH*HID + HID + HID)   // 5440 total B-matrix columns

// ---------------- device scratch (allowed: __device__ globals) ----------------
__device__ float g_A[2][HID * NCOLS];        // rearranged [w2 | b2 | root] per param set
__device__ float g_h[2][N_EDGES * EH];       // edge MLP hidden, per param set
__device__ float g_Y[N_NODES * NCOLS];       // per-node contraction output
__device__ float g_accum[N_NODES * HID];     // message accumulator
__device__ float g_x[2][N_NODES * HID];      // layer ping-pong
__device__ float g_inv[N_NODES];             // 1/max(cnt,1)
__device__ int   g_cnt[N_NODES];
__device__ int   g_src[N_EDGES];
__device__ int   g_dst[N_EDGES];
__device__ int   g_flag;                     // 1 => edge_index stored as int32

// ---------------- init / edge-index normalization ----------------
__global__ void init_kernel() {
    int i = blockIdx.x * blockDim.x + threadIdx.x;
    if (i < N_NODES) g_cnt[i] = 0;
    if (i == 0) g_flag = 0;
}

// If data is int64, every odd 32-bit word is a zero high-half (indices < 2048).
// If int32, odd words are random indices -> some nonzero.
__global__ void detect_kernel(const int* __restrict__ raw) {
    int i = blockIdx.x * blockDim.x + threadIdx.x;   // 0..8191
    int idx = 2 * i + 1;                             // odd words in first 64KB (safe both ways)
    if (idx < 2 * N_EDGES) {
        if (raw[idx] != 0) atomicOr(&g_flag, 1);
    }
}

__global__ void build_edges_kernel(const void* __restrict__ eiraw) {
    int e = blockIdx.x * blockDim.x + threadIdx.x;
    if (e >= N_EDGES) return;
    int s, d;
    if (g_flag) {  // int32 storage
        const int* p = (const int*)eiraw;
        s = p[e]; d = p[N_EDGES + e];
    } else {       // int64 storage
        const long long* p = (const long long*)eiraw;
        s = (int)p[e]; d = (int)p[N_EDGES + e];
    }
    g_src[e] = s;
    g_dst[e] = d;
    atomicAdd(&g_cnt[d], 1);
}

__global__ void inv_kernel() {
    int n = blockIdx.x * blockDim.x + threadIdx.x;
    if (n < N_NODES) g_inv[n] = 1.0f / fmaxf((float)g_cnt[n], 1.0f);
}

// ---------------- param rearrangement: A[i, c] ----------------
// c <  5120 : A[i, k*160+o] = w2[k, i*160+o]
// c <  5280 : A[i, 5120+o]  = b2[i*160+o]
// else      : A[i, 5280+o]  = root[i*160+o]
__global__ void build_A_kernel(const float* __restrict__ w2,
                               const float* __restrict__ b2,
                               const float* __restrict__ root, int slot) {
    int idx = blockIdx.x * blockDim.x + threadIdx.x;
    if (idx >= HID * NCOLS) return;
    int i = idx / NCOLS;
    int c = idx % NCOLS;
    float v;
    if (c < COL_B2) {
        int k = c / HID, o = c % HID;
        v = w2[k * NW + i * HID + o];
    } else if (c < COL_ROOT) {
        v = b2[i * HID + (c - COL_B2)];
    } else {
        v = root[i * HID + (c - COL_ROOT)];
    }
    g_A[slot][idx] = v;
}

// ---------------- edge MLP: h = relu(edge_attr @ w1 + b1) ----------------
__global__ void h_kernel(const float* __restrict__ ea,
                         const float* __restrict__ w1,
                         const float* __restrict__ b1, int slot) {
    __shared__ float sw[EDGE_DIM * EH];
    __shared__ float sb[EH];
    int t = threadIdx.x;
    for (int i = t; i < EDGE_DIM * EH; i += blockDim.x) sw[i] = w1[i];
    if (t < EH) sb[t] = b1[t];
    __syncthreads();
    int j  = t & 31;
    int el = t >> 5;                     // 8 edges per 256-thread block
    int e  = blockIdx.x * 8 + el;
    if (e < N_EDGES) {
        float acc = sb[j];
        #pragma unroll
        for (int d = 0; d < EDGE_DIM; d++)
            acc += ea[e * EDGE_DIM + d] * sw[d * EH + j];
        g_h[slot][e * EH + j] = fmaxf(acc, 0.0f);
    }
}

// ---------------- main GEMM: Y[2048, 5440] = X[2048,160] @ A[160,5440] ----------------
#define BM 128
#define BN 128
#define BK 16
#define TM 8
#define TN 8

__global__ __launch_bounds__(256) void gemm_kernel(const float* __restrict__ xin,
                                                   int xsel, int aslot) {
    const float* __restrict__ X  = (xsel < 0) ? xin : g_x[xsel];
    const float* __restrict__ Bm = g_A[aslot];

    __shared__ float As[BK][BM + 4];
    __shared__ float Bs[BK][BN];

    int tid = threadIdx.x;
    int n0 = blockIdx.x * BN;
    int m0 = blockIdx.y * BM;
    int tx = tid % 16, ty = tid / 16;

    float acc[TM][TN];
    #pragma unroll
    for (int i = 0; i < TM; i++)
        #pragma unroll
        for (int j = 0; j < TN; j++) acc[i][j] = 0.0f;

    int arow = tid >> 2;           // 0..63
    int acol = (tid & 3) * 4;      // 0,4,8,12
    int brow = tid >> 5;           // 0..7
    int bcol = (tid & 31) * 4;     // 0..124

    for (int k0 = 0; k0 < HID; k0 += BK) {
        #pragma unroll
        for (int r = 0; r < 2; r++) {
            int m = arow + r * 64;
            float4 v = *(const float4*)(X + (size_t)(m0 + m) * HID + k0 + acol);
            As[acol + 0][m] = v.x;
            As[acol + 1][m] = v.y;
            As[acol + 2][m] = v.z;
            As[acol + 3][m] = v.w;
        }
        #pragma unroll
        for (int r = 0; r < 2; r++) {
            int kk = brow + r * 8;
            int col = n0 + bcol;
            float4 v = make_float4(0.f, 0.f, 0.f, 0.f);
            if (col < NCOLS)
                v = *(const float4*)(Bm + (size_t)(k0 + kk) * NCOLS + col);
            *(float4*)(&Bs[kk][bcol]) = v;
        }
        __syncthreads();
        #pragma unroll
        for (int k = 0; k < BK; k++) {
            float rm[TM], rn[TN];
            #pragma unroll
            for (int i = 0; i < TM; i++) rm[i] = As[k][ty * TM + i];
            #pragma unroll
            for (int j = 0; j < TN; j++) rn[j] = Bs[k][tx * TN + j];
            #pragma unroll
            for (int i = 0; i < TM; i++)
                #pragma unroll
                for (int j = 0; j < TN; j++) acc[i][j] += rm[i] * rn[j];
        }
        __syncthreads();
    }

    #pragma unroll
    for (int i = 0; i < TM; i++) {
        int m = m0 + ty * TM + i;
        #pragma unroll
        for (int j = 0; j < TN; j += 4) {
            int col = n0 + tx * TN + j;
            if (col < NCOLS) {
                float4 v = make_float4(acc[i][j], acc[i][j + 1],
                                       acc[i][j + 2], acc[i][j + 3]);
                *(float4*)(g_Y + (size_t)m * NCOLS + col) = v;
            }
        }
    }
}

// ---------------- zero accumulator ----------------
__global__ void zero_accum_kernel() {
    int i = blockIdx.x * blockDim.x + threadIdx.x;
    if (i < N_NODES * HID) g_accum[i] = 0.0f;
}

// ---------------- per-edge message + scatter ----------------
// msg_e[o] = Y[src, 5120+o] + sum_k h_e[k] * Y[src, k*160+o] ; accum[dst,o] += msg
__global__ __launch_bounds__(HID) void edge_kernel(int slot) {
    __shared__ float sh[EH];
    __shared__ int s_src, s_dst;
    int e = blockIdx.x;
    int t = threadIdx.x;
    if (t < EH) sh[t] = g_h[slot][e * EH + t];
    if (t == 0) { s_src = g_src[e]; s_dst = g_dst[e]; }
    __syncthreads();
    const float* Yr = g_Y + (size_t)s_src * NCOLS;
    float msg = Yr[COL_B2 + t];
    #pragma unroll
    for (int k = 0; k < EH; k++) msg += sh[k] * Yr[k * HID + t];
    atomicAdd(&g_accum[s_dst * HID + t], msg);
}

// ---------------- finalize: out = act(accum*inv + root_term + bias) ----------------
__global__ void final_kernel(const float* __restrict__ bias, int outsel,
                             float* __restrict__ dout, int relu) {
    int idx = blockIdx.x * blockDim.x + threadIdx.x;
    if (idx >= N_NODES * HID) return;
    int n = idx / HID, o = idx % HID;
    float v = g_accum[idx] * g_inv[n] + g_Y[(size_t)n * NCOLS + COL_ROOT + o] + bias[o];
    if (relu) v = fmaxf(v, 0.0f);
    float* dst = (outsel == 2) ? dout : g_x[outsel];
    dst[idx] = v;
}

// ---------------- launch ----------------
extern "C" void kernel_launch(void* const* d_in, const int* in_sizes, int n_in,
                              void* d_out, int out_size) {
    const float* x       = (const float*)d_in[0];
    const float* ea      = (const float*)d_in[1];
    const float* w1_a    = (const float*)d_in[2];
    const float* b1_a    = (const float*)d_in[3];
    const float* w2_a    = (const float*)d_in[4];
    const float* b2_a    = (const float*)d_in[5];
    const float* root_a  = (const float*)d_in[6];
    const float* bias_a  = (const float*)d_in[7];
    const float* w1_b    = (const float*)d_in[8];
    const float* b1_b    = (const float*)d_in[9];
    const float* w2_b    = (const float*)d_in[10];
    const float* b2_b    = (const float*)d_in[11];
    const float* root_b  = (const float*)d_in[12];
    const float* bias_b  = (const float*)d_in[13];
    const void*  eidx    = d_in[14];
    float* out = (float*)d_out;

    // ---- setup (deterministic, every call) ----
    init_kernel<<<(N_NODES + 255) / 256, 256>>>();
    detect_kernel<<<(N_EDGES + 255) / 256, 256>>>((const int*)eidx);
    build_edges_kernel<<<(N_EDGES + 255) / 256, 256>>>(eidx);
    inv_kernel<<<(N_NODES + 255) / 256, 256>>>();

    int aElems = HID * NCOLS;
    build_A_kernel<<<(aElems + 255) / 256, 256>>>(w2_a, b2_a, root_a, 0);
    build_A_kernel<<<(aElems + 255) / 256, 256>>>(w2_b, b2_b, root_b, 1);

    h_kernel<<<N_EDGES / 8, 256>>>(ea, w1_a, b1_a, 0);
    h_kernel<<<N_EDGES / 8, 256>>>(ea, w1_b, b1_b, 1);

    dim3 gemm_grid((NCOLS + BN - 1) / BN, N_NODES / BM);   // (43, 16)
    int nh = N_NODES * HID;

    // ---- layer 0 (params a), relu ----
    gemm_kernel<<<gemm_grid, 256>>>(x, -1, 0);
    zero_accum_kernel<<<(nh + 255) / 256, 256>>>();
    edge_kernel<<<N_EDGES, HID>>>(0);
    final_kernel<<<(nh + 255) / 256, 256>>>(bias_a, 0, out, 1);

    // ---- layer 1 (params b), relu ----
    gemm_kernel<<<gemm_grid, 256>>>(nullptr, 0, 1);
    zero_accum_kernel<<<(nh + 255) / 256, 256>>>();
    edge_kernel<<<N_EDGES, HID>>>(1);
    final_kernel<<<(nh + 255) / 256, 256>>>(bias_b, 1, out, 1);

    // ---- layer 2 (params b), no relu, write d_out ----
    gemm_kernel<<<gemm_grid, 256>>>(nullptr, 1, 1);
    zero_accum_kernel<<<(nh + 255) / 256, 256>>>();
    edge_kernel<<<N_EDGES, HID>>>(1);
    final_kernel<<<(nh + 255) / 256, 256>>>(bias_b, 2, out, 0);
}

// round 2
// speedup vs baseline: 2.0547x; 2.0547x over previous
#include <cuda_runtime.h>
#include <cstdint>

#define N_NODES 2048
#define N_EDGES 8192
#define EDGE_DIM 10
#define EH 32
#define HID 160
#define NW (HID*HID)                 // 25600
#define COL_B2 (EH*HID)              // 5120 : start of b2-term columns
#define COL_ROOT (EH*HID + HID)      // 5280 : start of root-term columns
#define NCOLS (EH*HID + HID + HID)   // 5440 total B-matrix columns

// ---------------- device scratch ----------------
__device__ float g_A[2][HID * NCOLS];        // rearranged [w2 | b2 | root] per param set
__device__ float g_h[2][N_EDGES * EH];       // edge MLP hidden, per param set
__device__ float g_Y[N_NODES * NCOLS];       // per-node contraction output
__device__ float g_accum[N_NODES * HID];     // message accumulator
__device__ float g_x[2][N_NODES * HID];      // layer ping-pong
__device__ float g_inv[N_NODES];             // 1/max(cnt,1)
__device__ int   g_cnt[N_NODES];
__device__ int   g_src[N_EDGES];
__device__ int   g_dst[N_EDGES];
__device__ int   g_flag;                     // 1 => edge_index stored as int32

// ---------------- init / edge-index normalization ----------------
__global__ void init_kernel() {
    int i = blockIdx.x * blockDim.x + threadIdx.x;
    if (i < N_NODES) g_cnt[i] = 0;
    if (i == 0) g_flag = 0;
}

__global__ void detect_kernel(const int* __restrict__ raw) {
    int i = blockIdx.x * blockDim.x + threadIdx.x;
    int idx = 2 * i + 1;
    if (idx < 2 * N_EDGES) {
        if (raw[idx] != 0) atomicOr(&g_flag, 1);
    }
}

__global__ void build_edges_kernel(const void* __restrict__ eiraw) {
    int e = blockIdx.x * blockDim.x + threadIdx.x;
    if (e >= N_EDGES) return;
    int s, d;
    if (g_flag) {
        const int* p = (const int*)eiraw;
        s = p[e]; d = p[N_EDGES + e];
    } else {
        const long long* p = (const long long*)eiraw;
        s = (int)p[e]; d = (int)p[N_EDGES + e];
    }
    g_src[e] = s;
    g_dst[e] = d;
    atomicAdd(&g_cnt[d], 1);
}

__global__ void inv_kernel() {
    int n = blockIdx.x * blockDim.x + threadIdx.x;
    if (n < N_NODES) g_inv[n] = 1.0f / fmaxf((float)g_cnt[n], 1.0f);
}

// ---------------- param rearrangement ----------------
__global__ void build_A_kernel(const float* __restrict__ w2,
                               const float* __restrict__ b2,
                               const float* __restrict__ root, int slot) {
    int idx = blockIdx.x * blockDim.x + threadIdx.x;
    if (idx >= HID * NCOLS) return;
    int i = idx / NCOLS;
    int c = idx % NCOLS;
    float v;
    if (c < COL_B2) {
        int k = c / HID, o = c % HID;
        v = w2[k * NW + i * HID + o];
    } else if (c < COL_ROOT) {
        v = b2[i * HID + (c - COL_B2)];
    } else {
        v = root[i * HID + (c - COL_ROOT)];
    }
    g_A[slot][idx] = v;
}

// ---------------- edge MLP ----------------
__global__ void h_kernel(const float* __restrict__ ea,
                         const float* __restrict__ w1,
                         const float* __restrict__ b1, int slot) {
    __shared__ float sw[EDGE_DIM * EH];
    __shared__ float sb[EH];
    int t = threadIdx.x;
    for (int i = t; i < EDGE_DIM * EH; i += blockDim.x) sw[i] = w1[i];
    if (t < EH) sb[t] = b1[t];
    __syncthreads();
    int j  = t & 31;
    int el = t >> 5;
    int e  = blockIdx.x * 8 + el;
    if (e < N_EDGES) {
        float acc = sb[j];
        #pragma unroll
        for (int d = 0; d < EDGE_DIM; d++)
            acc += ea[e * EDGE_DIM + d] * sw[d * EH + j];
        g_h[slot][e * EH + j] = fmaxf(acc, 0.0f);
    }
}

// ---------------- TF32 tensor-core GEMM ----------------
// Y[2048, 5440] = X[2048,160] @ A[160,5440]
// CTA tile 128x128, 8 warps of 64x32, BK=32, mma.sync.m16n8k8.tf32
#define BM 128
#define BN 128
#define BK 32
#define AS_STRIDE 36    // [m][k] pad: frag bank = (4g+tig) -> conflict-free
#define BS_STRIDE 136   // [k][n] pad: frag bank = (8tig+g) -> conflict-free

__device__ __forceinline__ uint32_t f2tf32(float f) {
    uint32_t u;
    asm("cvt.rna.tf32.f32 %0, %1;" : "=r"(u) : "f"(f));
    return u;
}

__device__ __forceinline__ void mma_tf32(float* d, const uint32_t* a, const uint32_t* b) {
    asm volatile(
        "mma.sync.aligned.m16n8k8.row.col.f32.tf32.tf32.f32 "
        "{%0,%1,%2,%3}, {%4,%5,%6,%7}, {%8,%9}, {%0,%1,%2,%3};"
        : "+f"(d[0]), "+f"(d[1]), "+f"(d[2]), "+f"(d[3])
        : "r"(a[0]), "r"(a[1]), "r"(a[2]), "r"(a[3]), "r"(b[0]), "r"(b[1]));
}

__global__ __launch_bounds__(256, 2) void gemm_kernel(const float* __restrict__ xin,
                                                      int xsel, int aslot) {
    const float* __restrict__ X  = (xsel < 0) ? xin : g_x[xsel];
    const float* __restrict__ Bm = g_A[aslot];

    __shared__ uint32_t As[BM * AS_STRIDE];   // [m][k], tf32
    __shared__ uint32_t Bs[BK * BS_STRIDE];   // [k][n], tf32

    int tid  = threadIdx.x;
    int lane = tid & 31;
    int w    = tid >> 5;
    int wm   = w & 1;          // 2 warps in M
    int wn   = w >> 1;         // 4 warps in N
    int g    = lane >> 2;      // 0..7
    int tig  = lane & 3;       // 0..3

    int n0 = blockIdx.x * BN;
    int m0 = blockIdx.y * BM;

    float acc[4][4][4];
    #pragma unroll
    for (int i = 0; i < 4; i++)
        #pragma unroll
        for (int j = 0; j < 4; j++)
            #pragma unroll
            for (int r = 0; r < 4; r++) acc[i][j][r] = 0.0f;

    for (int k0 = 0; k0 < HID; k0 += BK) {
        // ---- stage A: 128 rows x 32 k = 1024 float4, 4 per thread ----
        #pragma unroll
        for (int i = 0; i < 4; i++) {
            int s   = tid + 256 * i;        // 0..1023
            int row = s >> 3;               // 8 float4 per row
            int col = (s & 7) * 4;
            float4 v = *(const float4*)(X + (size_t)(m0 + row) * HID + k0 + col);
            uint32_t* p = &As[row * AS_STRIDE + col];
            uint4 u = make_uint4(f2tf32(v.x), f2tf32(v.y), f2tf32(v.z), f2tf32(v.w));
            *(uint4*)p = u;
        }
        // ---- stage B: 32 k-rows x 128 n = 1024 float4, 4 per thread ----
        #pragma unroll
        for (int i = 0; i < 4; i++) {
            int s   = tid + 256 * i;
            int row = s >> 5;               // 32 float4 per row
            int col = (s & 31) * 4;
            float4 v = make_float4(0.f, 0.f, 0.f, 0.f);
            if (n0 + col < NCOLS)
                v = *(const float4*)(Bm + (size_t)(k0 + row) * NCOLS + n0 + col);
            uint4 u = make_uint4(f2tf32(v.x), f2tf32(v.y), f2tf32(v.z), f2tf32(v.w));
            *(uint4*)&Bs[row * BS_STRIDE + col] = u;
        }
        __syncthreads();

        // ---- mainloop: 4 k-steps of 8 ----
        #pragma unroll
        for (int ks = 0; ks < 4; ks++) {
            int ck = ks * 8;
            uint32_t af[4][4];
            #pragma unroll
            for (int mt = 0; mt < 4; mt++) {
                int rb = wm * 64 + mt * 16;
                af[mt][0] = As[(rb + g)     * AS_STRIDE + ck + tig];
                af[mt][1] = As[(rb + g + 8) * AS_STRIDE + ck + tig];
                af[mt][2] = As[(rb + g)     * AS_STRIDE + ck + tig + 4];
                af[mt][3] = As[(rb + g + 8) * AS_STRIDE + ck + tig + 4];
            }
            uint32_t bf[4][2];
            #pragma unroll
            for (int nt = 0; nt < 4; nt++) {
                int nc = wn * 32 + nt * 8 + g;
                bf[nt][0] = Bs[(ck + tig)     * BS_STRIDE + nc];
                bf[nt][1] = Bs[(ck + tig + 4) * BS_STRIDE + nc];
            }
            #pragma unroll
            for (int mt = 0; mt < 4; mt++)
                #pragma unroll
                for (int nt = 0; nt < 4; nt++)
                    mma_tf32(acc[mt][nt], af[mt], bf[nt]);
        }
        __syncthreads();
    }

    // ---- epilogue ----
    #pragma unroll
    for (int mt = 0; mt < 4; mt++) {
        int row = m0 + wm * 64 + mt * 16 + g;
        #pragma unroll
        for (int nt = 0; nt < 4; nt++) {
            int col = n0 + wn * 32 + nt * 8 + 2 * tig;
            if (col < NCOLS) {
                *(float2*)(g_Y + (size_t)row * NCOLS + col) =
                    make_float2(acc[mt][nt][0], acc[mt][nt][1]);
                *(float2*)(g_Y + (size_t)(row + 8) * NCOLS + col) =
                    make_float2(acc[mt][nt][2], acc[mt][nt][3]);
            }
        }
    }
}

// ---------------- zero accumulator ----------------
__global__ void zero_accum_kernel() {
    int i = blockIdx.x * blockDim.x + threadIdx.x;
    if (i < N_NODES * HID) g_accum[i] = 0.0f;
}

// ---------------- per-edge message + scatter ----------------
__global__ __launch_bounds__(HID) void edge_kernel(int slot) {
    __shared__ float sh[EH];
    __shared__ int s_src, s_dst;
    int e = blockIdx.x;
    int t = threadIdx.x;
    if (t < EH) sh[t] = g_h[slot][e * EH + t];
    if (t == 0) { s_src = g_src[e]; s_dst = g_dst[e]; }
    __syncthreads();
    const float* Yr = g_Y + (size_t)s_src * NCOLS;
    float msg = Yr[COL_B2 + t];
    #pragma unroll
    for (int k = 0; k < EH; k++) msg += sh[k] * Yr[k * HID + t];
    atomicAdd(&g_accum[s_dst * HID + t], msg);
}

// ---------------- finalize ----------------
__global__ void final_kernel(const float* __restrict__ bias, int outsel,
                             float* __restrict__ dout, int relu) {
    int idx = blockIdx.x * blockDim.x + threadIdx.x;
    if (idx >= N_NODES * HID) return;
    int n = idx / HID, o = idx % HID;
    float v = g_accum[idx] * g_inv[n] + g_Y[(size_t)n * NCOLS + COL_ROOT + o] + bias[o];
    if (relu) v = fmaxf(v, 0.0f);
    float* dst = (outsel == 2) ? dout : g_x[outsel];
    dst[idx] = v;
}

// ---------------- launch ----------------
extern "C" void kernel_launch(void* const* d_in, const int* in_sizes, int n_in,
                              void* d_out, int out_size) {
    const float* x       = (const float*)d_in[0];
    const float* ea      = (const float*)d_in[1];
    const float* w1_a    = (const float*)d_in[2];
    const float* b1_a    = (const float*)d_in[3];
    const float* w2_a    = (const float*)d_in[4];
    const float* b2_a    = (const float*)d_in[5];
    const float* root_a  = (const float*)d_in[6];
    const float* bias_a  = (const float*)d_in[7];
    const float* w1_b    = (const float*)d_in[8];
    const float* b1_b    = (const float*)d_in[9];
    const float* w2_b    = (const float*)d_in[10];
    const float* b2_b    = (const float*)d_in[11];
    const float* root_b  = (const float*)d_in[12];
    const float* bias_b  = (const float*)d_in[13];
    const void*  eidx    = d_in[14];
    float* out = (float*)d_out;

    init_kernel<<<(N_NODES + 255) / 256, 256>>>();
    detect_kernel<<<(N_EDGES + 255) / 256, 256>>>((const int*)eidx);
    build_edges_kernel<<<(N_EDGES + 255) / 256, 256>>>(eidx);
    inv_kernel<<<(N_NODES + 255) / 256, 256>>>();

    int aElems = HID * NCOLS;
    build_A_kernel<<<(aElems + 255) / 256, 256>>>(w2_a, b2_a, root_a, 0);
    build_A_kernel<<<(aElems + 255) / 256, 256>>>(w2_b, b2_b, root_b, 1);

    h_kernel<<<N_EDGES / 8, 256>>>(ea, w1_a, b1_a, 0);
    h_kernel<<<N_EDGES / 8, 256>>>(ea, w1_b, b1_b, 1);

    dim3 gemm_grid((NCOLS + BN - 1) / BN, N_NODES / BM);   // (43, 16)
    int nh = N_NODES * HID;

    // ---- layer 0 (params a), relu ----
    gemm_kernel<<<gemm_grid, 256>>>(x, -1, 0);
    zero_accum_kernel<<<(nh + 255) / 256, 256>>>();
    edge_kernel<<<N_EDGES, HID>>>(0);
    final_kernel<<<(nh + 255) / 256, 256>>>(bias_a, 0, out, 1);

    // ---- layer 1 (params b), relu ----
    gemm_kernel<<<gemm_grid, 256>>>(nullptr, 0, 1);
    zero_accum_kernel<<<(nh + 255) / 256, 256>>>();
    edge_kernel<<<N_EDGES, HID>>>(1);
    final_kernel<<<(nh + 255) / 256, 256>>>(bias_b, 1, out, 1);

    // ---- layer 2 (params b), no relu, write d_out ----
    gemm_kernel<<<gemm_grid, 256>>>(nullptr, 1, 1);
    zero_accum_kernel<<<(nh + 255) / 256, 256>>>();
    edge_kernel<<<N_EDGES, HID>>>(1);
    final_kernel<<<(nh + 255) / 256, 256>>>(bias_b, 2, out, 0);
}